// round 3
// baseline (speedup 1.0000x reference)
#include <cuda_runtime.h>
#include <math.h>

#define NB 2
#define NC 21
#define NP 4096
#define TAPS 71
#define RAD 35
#define QB 512

__device__ float g_K[NB][NP][NP];
__device__ float g_feat[NB][NP][8];
__device__ float g_U[NB][NC][NP];
__device__ float g_q[NB][NC][NP];
__device__ float g_tmp[NB][NC][NP];
__device__ float g_comb[NB][NC][NP];
__device__ float g_qbf[NB][64][NC][NP];
__device__ float g_g1[TAPS];

__device__ __forceinline__ float fexp2(float t) {
    t = fmaxf(t, -120.0f);
    float z  = t + 12582912.0f;
    int   ei = __float_as_int(z) - 0x4B400000;
    float f  = t - (z - 12582912.0f);
    float p  = fmaf(f, 0.001333355814642f, 0.009618129107629f);
    p = fmaf(f, p, 0.055504108664822f);
    p = fmaf(f, p, 0.240226506959101f);
    p = fmaf(f, p, 0.693147180559945f);
    p = fmaf(f, p, 1.0f);
    return __int_as_float(__float_as_int(p) + (ei << 23));
}

__global__ void prep_kernel(const float* __restrict__ unary,
                            const float* __restrict__ ref,
                            const float* __restrict__ kstd) {
    int t = blockIdx.x * 256 + threadIdx.x;
    if (t >= NB * NP) return;
    int n = t >> 12, p = t & (NP - 1);
    int y = p >> 6, x = p & 63;
    const float SQ = 1.2011224087864498f; // sqrt(log2 e)
    float f[5];
    f[0] = (float)y * (SQ / kstd[0]);
    f[1] = (float)x * (SQ / kstd[1]);
    f[2] = ref[(n * 3 + 0) * NP + p] * (SQ / kstd[2]);
    f[3] = ref[(n * 3 + 1) * NP + p] * (SQ / kstd[3]);
    f[4] = ref[(n * 3 + 2) * NP + p] * (SQ / kstd[4]);
    float a = 0.f;
#pragma unroll
    for (int k = 0; k < 5; k++) { g_feat[n][p][k] = f[k]; a = fmaf(f[k], f[k], a); }
    g_feat[n][p][5] = 0.5f * a;
    g_feat[n][p][6] = 0.f; g_feat[n][p][7] = 0.f;

    float pc[NC]; float s = 0.f;
#pragma unroll
    for (int c = 0; c < NC; c++) {
        float u = unary[(n * NC + c) * NP + p];
        u = fminf(fmaxf(u, 1e-5f), 1.0f);
        pc[c] = u; s += u;
        g_U[n][c][p] = logf(u);
    }
    float inv = 1.0f / s;
#pragma unroll
    for (int c = 0; c < NC; c++) g_q[n][c][p] = pc[c] * inv;
}

// gk = outer(r, r) with r = row sums (exact separable factor)
__global__ void g1_kernel(const float* __restrict__ gk) {
    int t = threadIdx.x;
    if (t < TAPS) {
        float s = 0.f;
        for (int j = 0; j < TAPS; j++) s += gk[t * TAPS + j];
        g_g1[t] = s;
    }
}

__global__ __launch_bounds__(256) void buildk_kernel() {
    __shared__ float fp[64][8];
    __shared__ float fq[64][8];
    int n = blockIdx.z;
    int P0 = blockIdx.y * 64, Q0 = blockIdx.x * 64;
    for (int i = threadIdx.x; i < 64 * 8; i += 256) {
        int r = i >> 3, k = i & 7;
        fp[r][k] = g_feat[n][P0 + r][k];
        fq[r][k] = g_feat[n][Q0 + r][k];
    }
    __syncthreads();
    int ql = threadIdx.x & 63;
    int pg = threadIdx.x >> 6;
    float q0 = fq[ql][0], q1 = fq[ql][1], q2 = fq[ql][2];
    float q3 = fq[ql][3], q4 = fq[ql][4], qa = fq[ql][5];
#pragma unroll
    for (int k = 0; k < 16; k++) {
        int pl = pg * 16 + k;
        float4 a4 = *(const float4*)&fp[pl][0];
        float2 a2 = *(const float2*)&fp[pl][4];
        float acc = -(a2.y + qa);
        acc = fmaf(a4.x, q0, acc);
        acc = fmaf(a4.y, q1, acc);
        acc = fmaf(a4.z, q2, acc);
        acc = fmaf(a4.w, q3, acc);
        acc = fmaf(a2.x, q4, acc);
        g_K[n][P0 + pl][Q0 + ql] = fexp2(acc); // = exp(-0.5*max(d2,0))
    }
}

// partial[n][slot][c][p] = sum over warp's 64-q window of K[p][q]*q[c][q]
__global__ __launch_bounds__(256, 2) void gemm_kernel() {
    __shared__ float qs[NC * QB];
    int n = blockIdx.z;
    int pb = blockIdx.x * 64;
    int qb = blockIdx.y * QB;
    for (int i = threadIdx.x; i < NC * QB; i += 256)
        qs[i] = g_q[n][i >> 9][qb + (i & 511)];
    __syncthreads();
    int w = threadIdx.x >> 5, l = threadIdx.x & 31;
    int q0 = w * 64;
    float acc[2][NC];
#pragma unroll
    for (int j = 0; j < 2; j++)
#pragma unroll
        for (int c = 0; c < NC; c++) acc[j][c] = 0.f;

    const float* K0 = &g_K[n][pb + l][qb + q0];
    const float* K1 = K0 + 32 * NP;
    float4 kv0 = *(const float4*)K0;
    float4 kv1 = *(const float4*)K1;
#pragma unroll 1
    for (int ch = 0; ch < 16; ch++) {
        float4 kn0, kn1;
        if (ch < 15) {
            kn0 = *(const float4*)(K0 + (ch + 1) * 4);
            kn1 = *(const float4*)(K1 + (ch + 1) * 4);
        }
#pragma unroll
        for (int c = 0; c < NC; c++) {
            float4 qv = *(const float4*)&qs[c * QB + q0 + ch * 4];
            acc[0][c] = fmaf(kv0.x, qv.x, acc[0][c]);
            acc[0][c] = fmaf(kv0.y, qv.y, acc[0][c]);
            acc[0][c] = fmaf(kv0.z, qv.z, acc[0][c]);
            acc[0][c] = fmaf(kv0.w, qv.w, acc[0][c]);
            acc[1][c] = fmaf(kv1.x, qv.x, acc[1][c]);
            acc[1][c] = fmaf(kv1.y, qv.y, acc[1][c]);
            acc[1][c] = fmaf(kv1.z, qv.z, acc[1][c]);
            acc[1][c] = fmaf(kv1.w, qv.w, acc[1][c]);
        }
        kv0 = kn0; kv1 = kn1;
    }
    int slot = blockIdx.y * 8 + w;
#pragma unroll
    for (int j = 0; j < 2; j++)
#pragma unroll
        for (int c = 0; c < NC; c++)
            g_qbf[n][slot][c][pb + j * 32 + l] = acc[j][c];
}

__global__ void convy_kernel() {
    int t = blockIdx.x * 256 + threadIdx.x; // < NC*NP
    int n = blockIdx.y;
    int c = t >> 12, p = t & 4095;
    int y = p >> 6, x = p & 63;
    int j0 = max(0, y - RAD), j1 = min(63, y + RAD);
    const float* col = &g_q[n][c][x];
    float s = 0.f;
    for (int j = j0; j <= j1; j++) s = fmaf(g_g1[j - y + RAD], col[j * 64], s);
    g_tmp[n][c][p] = s;
}

__global__ void combine_kernel() {
    int t = blockIdx.x * 256 + threadIdx.x; // < NC*NP
    int n = blockIdx.y;
    int c = t >> 12, p = t & 4095;
    int y = p >> 6, x = p & 63;
    int j0 = max(0, x - RAD), j1 = min(63, x + RAD);
    const float* row = &g_tmp[n][c][y * 64];
    float s = 0.f;
    for (int j = j0; j <= j1; j++) s = fmaf(g_g1[j - x + RAD], row[j], s);
    float b = 0.f;
#pragma unroll 16
    for (int sl = 0; sl < 64; sl++) b += g_qbf[n][sl][c][p];
    g_comb[n][c][p] = fmaf(4.0f, b, 2.0f * s); // COMPAT_BF, COMPAT_SPATIAL
}

__global__ void fuse_kernel(float* __restrict__ dout, int last) {
    int t = blockIdx.x * 256 + threadIdx.x;
    if (t >= NB * NP) return;
    int n = t >> 12, p = t & 4095;
    float logit[NC]; float m = -1e30f;
#pragma unroll
    for (int c = 0; c < NC; c++) {
        float lg = g_U[n][c][p] + g_comb[n][c][p];
        logit[c] = lg; m = fmaxf(m, lg);
    }
    float sum = 0.f;
#pragma unroll
    for (int c = 0; c < NC; c++) { float e = __expf(logit[c] - m); logit[c] = e; sum += e; }
    float inv = 1.0f / sum;
#pragma unroll
    for (int c = 0; c < NC; c++) {
        float qq = logit[c] * inv;
        g_q[n][c][p] = qq;
        if (last) dout[(n * NC + c) * NP + p] = qq;
    }
}

extern "C" void kernel_launch(void* const* d_in, const int* in_sizes, int n_in,
                              void* d_out, int out_size) {
    const float* unary = (const float*)d_in[0];
    const float* ref   = (const float*)d_in[1];
    const float* gk    = (const float*)d_in[2];
    const float* kstd  = (const float*)d_in[3];
    float* dout = (float*)d_out;

    prep_kernel<<<32, 256>>>(unary, ref, kstd);
    g1_kernel<<<1, 128>>>(gk);
    buildk_kernel<<<dim3(64, 64, NB), 256>>>();
    for (int it = 0; it < 5; it++) {
        gemm_kernel<<<dim3(64, 8, NB), 256>>>();
        convy_kernel<<<dim3(336, NB), 256>>>();
        combine_kernel<<<dim3(336, NB), 256>>>();
        fuse_kernel<<<32, 256>>>(dout, it == 4);
    }
}

// round 4
// speedup vs baseline: 1.0009x; 1.0009x over previous
#include <cuda_runtime.h>
#include <math.h>

#define NB 2
#define NC 21
#define NP 4096
#define TAPS 71
#define RAD 35
#define QB 512

__device__ float g_K[NB][NP][NP];
__device__ float g_feat[NB][NP][8];
__device__ float g_U[NB][NC][NP];
__device__ float g_q[NB][NC][NP];
__device__ float g_tmp[NB][NC][NP];
__device__ float g_comb[NB][NC][NP];
__device__ float g_qbf[NB][8][NC][NP];
__device__ float g_g1[TAPS];

__device__ __forceinline__ float fexp2(float t) {
    t = fmaxf(t, -120.0f);
    float z  = t + 12582912.0f;
    int   ei = __float_as_int(z) - 0x4B400000;
    float f  = t - (z - 12582912.0f);
    float p  = fmaf(f, 0.001333355814642f, 0.009618129107629f);
    p = fmaf(f, p, 0.055504108664822f);
    p = fmaf(f, p, 0.240226506959101f);
    p = fmaf(f, p, 0.693147180559945f);
    p = fmaf(f, p, 1.0f);
    return __int_as_float(__float_as_int(p) + (ei << 23));
}

__global__ void prep_kernel(const float* __restrict__ unary,
                            const float* __restrict__ ref,
                            const float* __restrict__ kstd) {
    int t = blockIdx.x * 256 + threadIdx.x;
    if (t >= NB * NP) return;
    int n = t >> 12, p = t & (NP - 1);
    int y = p >> 6, x = p & 63;
    const float SQ = 1.2011224087864498f; // sqrt(log2 e)
    float f[5];
    f[0] = (float)y * (SQ / kstd[0]);
    f[1] = (float)x * (SQ / kstd[1]);
    f[2] = ref[(n * 3 + 0) * NP + p] * (SQ / kstd[2]);
    f[3] = ref[(n * 3 + 1) * NP + p] * (SQ / kstd[3]);
    f[4] = ref[(n * 3 + 2) * NP + p] * (SQ / kstd[4]);
    float a = 0.f;
#pragma unroll
    for (int k = 0; k < 5; k++) { g_feat[n][p][k] = f[k]; a = fmaf(f[k], f[k], a); }
    g_feat[n][p][5] = 0.5f * a;
    g_feat[n][p][6] = 0.f; g_feat[n][p][7] = 0.f;

    float pc[NC]; float s = 0.f;
#pragma unroll
    for (int c = 0; c < NC; c++) {
        float u = unary[(n * NC + c) * NP + p];
        u = fminf(fmaxf(u, 1e-5f), 1.0f);
        pc[c] = u; s += u;
        g_U[n][c][p] = logf(u);
    }
    float inv = 1.0f / s;
#pragma unroll
    for (int c = 0; c < NC; c++) g_q[n][c][p] = pc[c] * inv;
}

// gk = outer(r, r) with r = row sums (exact separable factor)
__global__ void g1_kernel(const float* __restrict__ gk) {
    int t = threadIdx.x;
    if (t < TAPS) {
        float s = 0.f;
        for (int j = 0; j < TAPS; j++) s += gk[t * TAPS + j];
        g_g1[t] = s;
    }
}

__global__ __launch_bounds__(256) void buildk_kernel() {
    __shared__ float fp[64][8];
    __shared__ float fq[64][8];
    int n = blockIdx.z;
    int P0 = blockIdx.y * 64, Q0 = blockIdx.x * 64;
    for (int i = threadIdx.x; i < 64 * 8; i += 256) {
        int r = i >> 3, k = i & 7;
        fp[r][k] = g_feat[n][P0 + r][k];
        fq[r][k] = g_feat[n][Q0 + r][k];
    }
    __syncthreads();
    int ql = threadIdx.x & 63;
    int pg = threadIdx.x >> 6;
    float q0 = fq[ql][0], q1 = fq[ql][1], q2 = fq[ql][2];
    float q3 = fq[ql][3], q4 = fq[ql][4], qa = fq[ql][5];
#pragma unroll
    for (int k = 0; k < 16; k++) {
        int pl = pg * 16 + k;
        float4 a4 = *(const float4*)&fp[pl][0];
        float2 a2 = *(const float2*)&fp[pl][4];
        float acc = -(a2.y + qa);
        acc = fmaf(a4.x, q0, acc);
        acc = fmaf(a4.y, q1, acc);
        acc = fmaf(a4.z, q2, acc);
        acc = fmaf(a4.w, q3, acc);
        acc = fmaf(a2.x, q4, acc);
        g_K[n][P0 + pl][Q0 + ql] = fexp2(acc); // = exp(-0.5*max(d2,0))
    }
}

// qbf_part[n][qblk][c][p] = sum over 512-q block of K[p][q]*q[c][q]
// 8 warps, each owns a 64-q window; lane owns p-rows {l, l+32}.
// Depth-4 software pipeline on K: 8 LDG.128 in flight/warp -> ~16KB/SM.
__global__ __launch_bounds__(256, 2) void gemm_kernel() {
    __shared__ float qs[NC * QB]; // 43KB, exactly reused for reduction (8*2*21*32 = 10752)
    int n = blockIdx.z;
    int pb = blockIdx.x * 64;
    int qb = blockIdx.y * QB;
    for (int i = threadIdx.x; i < NC * QB; i += 256)
        qs[i] = g_q[n][i >> 9][qb + (i & 511)];
    __syncthreads();
    int w = threadIdx.x >> 5, l = threadIdx.x & 31;
    int q0 = w * 64;
    float acc[2][NC];
#pragma unroll
    for (int j = 0; j < 2; j++)
#pragma unroll
        for (int c = 0; c < NC; c++) acc[j][c] = 0.f;

    const float4* K0 = (const float4*)&g_K[n][pb + l][qb + q0];
    const float4* K1 = K0 + 32 * (NP / 4);
    float4 b0[4], b1[4];
#pragma unroll
    for (int u = 0; u < 4; u++) { b0[u] = K0[u]; b1[u] = K1[u]; }

#pragma unroll 1
    for (int cc = 0; cc < 4; cc++) {
#pragma unroll
        for (int u = 0; u < 4; u++) {
            int ch = cc * 4 + u;
            float4 kv0 = b0[u], kv1 = b1[u];
            if (cc < 3) { b0[u] = K0[ch + 4]; b1[u] = K1[ch + 4]; }
            const float* qp = &qs[q0 + ch * 4];
#pragma unroll
            for (int c = 0; c < NC; c++) {
                float4 qv = *(const float4*)&qp[c * QB];
                acc[0][c] = fmaf(kv0.x, qv.x, acc[0][c]);
                acc[0][c] = fmaf(kv0.y, qv.y, acc[0][c]);
                acc[0][c] = fmaf(kv0.z, qv.z, acc[0][c]);
                acc[0][c] = fmaf(kv0.w, qv.w, acc[0][c]);
                acc[1][c] = fmaf(kv1.x, qv.x, acc[1][c]);
                acc[1][c] = fmaf(kv1.y, qv.y, acc[1][c]);
                acc[1][c] = fmaf(kv1.z, qv.z, acc[1][c]);
                acc[1][c] = fmaf(kv1.w, qv.w, acc[1][c]);
            }
        }
    }
    // deterministic in-block cross-warp reduction (reuses qs)
    __syncthreads();
#pragma unroll
    for (int j = 0; j < 2; j++)
#pragma unroll
        for (int c = 0; c < NC; c++)
            qs[((w * 2 + j) * NC + c) * 32 + l] = acc[j][c];
    __syncthreads();
    for (int i = threadIdx.x; i < 2 * NC * 32; i += 256) {
        int lp = i & 31, c = (i >> 5) % NC, j = i / (NC * 32);
        float s = 0.f;
#pragma unroll
        for (int w2 = 0; w2 < 8; w2++) s += qs[((w2 * 2 + j) * NC + c) * 32 + lp];
        g_qbf[n][blockIdx.y][c][pb + j * 32 + lp] = s;
    }
}

__global__ void convy_kernel() {
    int t = blockIdx.x * 256 + threadIdx.x; // < NC*NP
    int n = blockIdx.y;
    int c = t >> 12, p = t & 4095;
    int y = p >> 6, x = p & 63;
    int j0 = max(0, y - RAD), j1 = min(63, y + RAD);
    const float* col = &g_q[n][c][x];
    float s = 0.f;
    for (int j = j0; j <= j1; j++) s = fmaf(g_g1[j - y + RAD], col[j * 64], s);
    g_tmp[n][c][p] = s;
}

__global__ void combine_kernel() {
    int t = blockIdx.x * 256 + threadIdx.x; // < NC*NP
    int n = blockIdx.y;
    int c = t >> 12, p = t & 4095;
    int y = p >> 6, x = p & 63;
    int j0 = max(0, x - RAD), j1 = min(63, x + RAD);
    const float* row = &g_tmp[n][c][y * 64];
    float s = 0.f;
    for (int j = j0; j <= j1; j++) s = fmaf(g_g1[j - x + RAD], row[j], s);
    float b = 0.f;
#pragma unroll
    for (int sl = 0; sl < 8; sl++) b += g_qbf[n][sl][c][p];
    g_comb[n][c][p] = fmaf(4.0f, b, 2.0f * s); // COMPAT_BF, COMPAT_SPATIAL
}

__global__ void fuse_kernel(float* __restrict__ dout, int last) {
    int t = blockIdx.x * 256 + threadIdx.x;
    if (t >= NB * NP) return;
    int n = t >> 12, p = t & 4095;
    float logit[NC]; float m = -1e30f;
#pragma unroll
    for (int c = 0; c < NC; c++) {
        float lg = g_U[n][c][p] + g_comb[n][c][p];
        logit[c] = lg; m = fmaxf(m, lg);
    }
    float sum = 0.f;
#pragma unroll
    for (int c = 0; c < NC; c++) { float e = __expf(logit[c] - m); logit[c] = e; sum += e; }
    float inv = 1.0f / sum;
#pragma unroll
    for (int c = 0; c < NC; c++) {
        float qq = logit[c] * inv;
        g_q[n][c][p] = qq;
        if (last) dout[(n * NC + c) * NP + p] = qq;
    }
}

extern "C" void kernel_launch(void* const* d_in, const int* in_sizes, int n_in,
                              void* d_out, int out_size) {
    const float* unary = (const float*)d_in[0];
    const float* ref   = (const float*)d_in[1];
    const float* gk    = (const float*)d_in[2];
    const float* kstd  = (const float*)d_in[3];
    float* dout = (float*)d_out;

    prep_kernel<<<32, 256>>>(unary, ref, kstd);
    g1_kernel<<<1, 128>>>(gk);
    buildk_kernel<<<dim3(64, 64, NB), 256>>>();
    for (int it = 0; it < 5; it++) {
        gemm_kernel<<<dim3(64, 8, NB), 256>>>();
        convy_kernel<<<dim3(336, NB), 256>>>();
        combine_kernel<<<dim3(336, NB), 256>>>();
        fuse_kernel<<<32, 256>>>(dout, it == 4);
    }
}